// round 3
// baseline (speedup 1.0000x reference)
#include <cuda_runtime.h>

#define NV  64
#define NP  2016      // 64*63/2
#define NQ  504       // NP/4
#define TPB 256
#define BPB 4         // batches per block

__global__ __launch_bounds__(TPB) void score_kernel(
    const float* __restrict__ views,     // [B, 64, 7]
    const float* __restrict__ pairs,     // [B, 2016, 3]
    const float* __restrict__ s_a1,
    const float* __restrict__ s_a2,
    const float* __restrict__ s_gsd,
    const float* __restrict__ s_scale,
    const float* __restrict__ s_nrm,
    const float* __restrict__ s_dist,
    float* __restrict__ out,             // [B]
    int B)
{
    const int tid = threadIdx.x;
    const int b0  = blockIdx.x * BPB;

    __shared__ float w[BPB][NV];
    __shared__ float warpsum[BPB][TPB / 32];

    // Scalar params pre-scaled by log2(e): exp(x) == exp2f(coef * x^2)
    const float L2E = 1.4426950408889634f;
    const float a1 = *s_a1;
    const float a2 = *s_a2;
    const float c_a1   = -0.5f * L2E / (a1 * a1);
    const float c_a2   = -0.5f * L2E / (a2 * a2);
    const float gs = *s_gsd;   const float c_gsd  = -0.5f * L2E / (gs * gs);
    const float sc = *s_scale; const float c_sc   = -0.5f * L2E / (sc * sc);
    const float ns = *s_nrm;   const float c_nrm  = -0.5f * L2E / (ns * ns);
    const float ds = *s_dist;  const float c_dist = -0.5f * L2E / (ds * ds);
    const float TH = 20.0f / 90.0f;

    // ---- w-prologue: 256 threads = 4 batches x 64 views, single pass ----
    {
        const int bb = tid >> 6;        // 0..3
        const int v  = tid & 63;        // 0..63
        const int b  = b0 + bb;
        if (b < B) {
            const float* vr = views + ((size_t)b * NV + v) * 7;
            float v0 = vr[0];
            float x4 = vr[4];
            float x5 = vr[5];
            float x6 = vr[6];
            float m  = (v0 == 1.0f) ? 1.0f : 0.0f;
            float x4sq = x4 * x4;
            float arg = fmaf(x4sq * x4sq, c_gsd,
                        fmaf(x5 * x5,     c_nrm,
                             (x6 * x6) *  c_dist));
            w[bb][v] = m * exp2f(arg);
        }
    }
    __syncthreads();

    // ---- hoisted (i,j) decode: depends only on tid, shared by all batches ----
    const int q0 = tid;
    const int q1 = tid + TPB;
    const bool has2 = (q1 < NQ);

    int i0, j0, i1 = 0, j1 = 0;
    {
        int p0 = 4 * q0;
        int i = (int)((127.0f - sqrtf((float)(16129 - 8 * p0))) * 0.5f);
        while (p0 < ((i * (127 - i)) >> 1)) --i;
        while (p0 >= (((i + 1) * (126 - i)) >> 1)) ++i;
        i0 = i; j0 = p0 - ((i * (127 - i)) >> 1) + i + 1;
    }
    if (has2) {
        int p0 = 4 * q1;
        int i = (int)((127.0f - sqrtf((float)(16129 - 8 * p0))) * 0.5f);
        while (p0 < ((i * (127 - i)) >> 1)) --i;
        while (p0 >= (((i + 1) * (126 - i)) >> 1)) ++i;
        i1 = i; j1 = p0 - ((i * (127 - i)) >> 1) + i + 1;
    }

    float acc[BPB];
    #pragma unroll
    for (int bb = 0; bb < BPB; ++bb) acc[bb] = 0.0f;

    // Process one quad of 4 pairs given data f0,f1,f2 and starting (i,j)
    #define PROC_QUAD(f0, f1, f2, istart, jstart, accref, wrow)                \
    {                                                                          \
        int i = (istart), j = (jstart);                                        \
        float pm[4] = { ((f0).x != 0.0f) ? 1.0f : 0.0f,                        \
                        ((f0).w != 0.0f) ? 1.0f : 0.0f,                        \
                        ((f1).z != 0.0f) ? 1.0f : 0.0f,                        \
                        ((f2).y != 0.0f) ? 1.0f : 0.0f };                      \
        float av[4] = { (f0).y, (f1).x, (f1).w, (f2).z };                      \
        float sv[4] = { (f0).z, (f1).y, (f2).x, (f2).w };                      \
        _Pragma("unroll")                                                      \
        for (int k = 0; k < 4; ++k) {                                          \
            float a = av[k];                                                   \
            float s = sv[k];                                                   \
            float m = (a == TH) ? 0.0f : pm[k];                                \
            float ca = (a < TH) ? c_a1 : c_a2;                                 \
            float arg = fmaf(a * a, ca, (s * s) * c_sc);                       \
            float e = exp2f(arg);                                              \
            accref = fmaf(m * e, (wrow)[i] * (wrow)[j], accref);               \
            ++j;                                                               \
            if (j == NV) { ++i; j = i + 1; }                                   \
        }                                                                      \
    }

    #pragma unroll
    for (int bb = 0; bb < BPB; ++bb) {
        const int b = b0 + bb;
        if (b >= B) break;
        const float4* pr = (const float4*)(pairs + (size_t)b * NP * 3);

        float4 A0 = __ldcs(&pr[3 * q0 + 0]);
        float4 A1 = __ldcs(&pr[3 * q0 + 1]);
        float4 A2 = __ldcs(&pr[3 * q0 + 2]);
        float4 Bq0, Bq1, Bq2;
        if (has2) {
            Bq0 = __ldcs(&pr[3 * q1 + 0]);
            Bq1 = __ldcs(&pr[3 * q1 + 1]);
            Bq2 = __ldcs(&pr[3 * q1 + 2]);
        }

        PROC_QUAD(A0, A1, A2, i0, j0, acc[bb], w[bb]);
        if (has2) {
            PROC_QUAD(Bq0, Bq1, Bq2, i1, j1, acc[bb], w[bb]);
        }
    }
    #undef PROC_QUAD

    // ---- fused epilogue: reduce 4 accumulators ----
    #pragma unroll
    for (int bb = 0; bb < BPB; ++bb) {
        float a = acc[bb];
        #pragma unroll
        for (int o = 16; o > 0; o >>= 1)
            a += __shfl_down_sync(0xffffffffu, a, o);
        if ((tid & 31) == 0) warpsum[bb][tid >> 5] = a;
    }
    __syncthreads();

    // 32 lanes finish: lane t handles batch t>>3, warpsum index t&7;
    // segmented 8-lane shuffle reduction.
    if (tid < 32) {
        const int bb = tid >> 3;
        const int k  = tid & 7;
        float p = warpsum[bb][k];
        p += __shfl_down_sync(0xffffffffu, p, 4);
        p += __shfl_down_sync(0xffffffffu, p, 2);
        p += __shfl_down_sync(0xffffffffu, p, 1);
        if (k == 0 && (b0 + bb) < B) out[b0 + bb] = p;
    }
}

extern "C" void kernel_launch(void* const* d_in, const int* in_sizes, int n_in,
                              void* d_out, int out_size) {
    const float* views  = (const float*)d_in[0];
    const float* pairs  = (const float*)d_in[1];
    // d_in[2] = point_attribute (unused by reference computation)
    const float* a1     = (const float*)d_in[3];
    const float* a2     = (const float*)d_in[4];
    const float* gsd    = (const float*)d_in[5];
    const float* scale  = (const float*)d_in[6];
    const float* nrm    = (const float*)d_in[7];
    const float* dist   = (const float*)d_in[8];
    float* out = (float*)d_out;

    int B = in_sizes[0] / (NV * 7);
    int nblocks = (B + BPB - 1) / BPB;
    score_kernel<<<nblocks, TPB>>>(views, pairs, a1, a2, gsd, scale, nrm, dist,
                                   out, B);
}

// round 4
// speedup vs baseline: 1.1951x; 1.1951x over previous
#include <cuda_runtime.h>

#define NV  64
#define NP  2016      // 64*63/2
#define NQ  504       // NP/4
#define TPB 256

__global__ __launch_bounds__(TPB, 6) void score_kernel(
    const float* __restrict__ views,     // [B, 64, 7]
    const float* __restrict__ pairs,     // [B, 2016, 3]
    const float* __restrict__ s_a1,
    const float* __restrict__ s_a2,
    const float* __restrict__ s_gsd,
    const float* __restrict__ s_scale,
    const float* __restrict__ s_nrm,
    const float* __restrict__ s_dist,
    float* __restrict__ out)             // [B]
{
    const int b   = blockIdx.x;
    const int tid = threadIdx.x;

    __shared__ float w[NV];
    __shared__ float warpsum[TPB / 32];

    // ---- 1) Fire the big streaming loads FIRST (93% of traffic) ----------
    const float4* pr = (const float4*)(pairs + (size_t)b * NP * 3);
    const int q0 = tid;
    int q1 = tid + TPB;
    const float vmask1 = (q1 < NQ) ? 1.0f : 0.0f;   // mask instead of branch
    if (q1 >= NQ) q1 = NQ - 1;                      // clamped valid address

    float4 A0 = __ldcs(&pr[3 * q0 + 0]);
    float4 A1 = __ldcs(&pr[3 * q0 + 1]);
    float4 A2 = __ldcs(&pr[3 * q0 + 2]);
    float4 B0 = __ldcs(&pr[3 * q1 + 0]);
    float4 B1 = __ldcs(&pr[3 * q1 + 1]);
    float4 B2 = __ldcs(&pr[3 * q1 + 2]);

    // ---- 2) Scalar params (uniform, L2-broadcast) + per-view weights -----
    const float L2E = 1.4426950408889634f;
    const float a1 = *s_a1;
    const float a2 = *s_a2;
    const float c_a1 = -0.5f * L2E / (a1 * a1);
    const float c_a2 = -0.5f * L2E / (a2 * a2);
    const float sc = *s_scale;
    const float c_sc = -0.5f * L2E / (sc * sc);
    const float TH = 20.0f / 90.0f;

    if (tid < NV) {
        const float gs = *s_gsd;   const float c_gsd  = -0.5f * L2E / (gs * gs);
        const float ns = *s_nrm;   const float c_nrm  = -0.5f * L2E / (ns * ns);
        const float ds = *s_dist;  const float c_dist = -0.5f * L2E / (ds * ds);
        const float* vr = views + ((size_t)b * NV + tid) * 7;
        float v0 = vr[0];
        float x4 = vr[4];
        float x5 = vr[5];
        float x6 = vr[6];
        float m  = (v0 == 1.0f) ? 1.0f : 0.0f;
        float x4sq = x4 * x4;
        float arg = fmaf(x4sq * x4sq, c_gsd,
                    fmaf(x5 * x5,     c_nrm,
                         (x6 * x6) *  c_dist));
        w[tid] = m * exp2f(arg);
    }

    // ---- 3) (i,j) decode overlaps the in-flight loads ---------------------
    int i0, j0, i1, j1;
    {
        int p0 = 4 * q0;
        int i = (int)((127.0f - sqrtf((float)(16129 - 8 * p0))) * 0.5f);
        while (p0 < ((i * (127 - i)) >> 1)) --i;
        while (p0 >= (((i + 1) * (126 - i)) >> 1)) ++i;
        i0 = i; j0 = p0 - ((i * (127 - i)) >> 1) + i + 1;
    }
    {
        int p0 = 4 * q1;
        int i = (int)((127.0f - sqrtf((float)(16129 - 8 * p0))) * 0.5f);
        while (p0 < ((i * (127 - i)) >> 1)) --i;
        while (p0 >= (((i + 1) * (126 - i)) >> 1)) ++i;
        i1 = i; j1 = p0 - ((i * (127 - i)) >> 1) + i + 1;
    }

    __syncthreads();

    float acc = 0.0f;

    #define PROC_QUAD(f0, f1, f2, istart, jstart, vmask)                       \
    {                                                                          \
        int i = (istart), j = (jstart);                                        \
        float pm[4] = { ((f0).x != 0.0f) ? (vmask) : 0.0f,                     \
                        ((f0).w != 0.0f) ? (vmask) : 0.0f,                     \
                        ((f1).z != 0.0f) ? (vmask) : 0.0f,                     \
                        ((f2).y != 0.0f) ? (vmask) : 0.0f };                   \
        float av[4] = { (f0).y, (f1).x, (f1).w, (f2).z };                      \
        float sv[4] = { (f0).z, (f1).y, (f2).x, (f2).w };                      \
        _Pragma("unroll")                                                      \
        for (int k = 0; k < 4; ++k) {                                          \
            float a = av[k];                                                   \
            float s = sv[k];                                                   \
            float m = (a == TH) ? 0.0f : pm[k];                                \
            float ca = (a < TH) ? c_a1 : c_a2;                                 \
            float arg = fmaf(a * a, ca, (s * s) * c_sc);                       \
            float e = exp2f(arg);                                              \
            acc = fmaf(m * e, w[i] * w[j], acc);                               \
            ++j;                                                               \
            if (j == NV) { ++i; j = i + 1; }                                   \
        }                                                                      \
    }

    PROC_QUAD(A0, A1, A2, i0, j0, 1.0f);
    PROC_QUAD(B0, B1, B2, i1, j1, vmask1);
    #undef PROC_QUAD

    // ---- 4) Block reduction ----------------------------------------------
    #pragma unroll
    for (int o = 16; o > 0; o >>= 1)
        acc += __shfl_down_sync(0xffffffffu, acc, o);
    if ((tid & 31) == 0) warpsum[tid >> 5] = acc;
    __syncthreads();
    if (tid < 8) {
        float p = warpsum[tid];
        p += __shfl_down_sync(0x000000ffu, p, 4);
        p += __shfl_down_sync(0x000000ffu, p, 2);
        p += __shfl_down_sync(0x000000ffu, p, 1);
        if (tid == 0) out[b] = p;
    }
}

extern "C" void kernel_launch(void* const* d_in, const int* in_sizes, int n_in,
                              void* d_out, int out_size) {
    const float* views  = (const float*)d_in[0];
    const float* pairs  = (const float*)d_in[1];
    // d_in[2] = point_attribute (unused by reference computation)
    const float* a1     = (const float*)d_in[3];
    const float* a2     = (const float*)d_in[4];
    const float* gsd    = (const float*)d_in[5];
    const float* scale  = (const float*)d_in[6];
    const float* nrm    = (const float*)d_in[7];
    const float* dist   = (const float*)d_in[8];
    float* out = (float*)d_out;

    int B = in_sizes[0] / (NV * 7);
    score_kernel<<<B, TPB>>>(views, pairs, a1, a2, gsd, scale, nrm, dist, out);
}